// round 4
// baseline (speedup 1.0000x reference)
#include <cuda_runtime.h>
#include <cuda_bf16.h>
#include <math.h>

#define Bn 8
#define Ln 4096
#define Hn 512
#define Nn 512
#define Mn 8192
#define KDIM 1024

#define XPAD 8448                                  // 8192 + 8192/32
#define SMEM_FFT ((XPAD + 4096) * (int)sizeof(float2))

// ---- device scratch (no allocations allowed) ----
__device__ float2 d_W[4096];
__device__ int    d_flags[64];
__device__ float  d_A[Hn * KDIM];
__device__ float  d_Bm[KDIM * Ln];
__device__ float  d_Kt[Hn * Ln];
__device__ float2 d_Kf[(size_t)Hn * Mn];
__device__ float  d_u[(size_t)Bn * Ln * Hn];
__device__ float  d_ut[(size_t)Bn * Hn * Ln];
__device__ float  d_yt[(size_t)Bn * Hn * Ln];

__device__ __forceinline__ float2 cadd(float2 a, float2 b){ return make_float2(a.x+b.x, a.y+b.y); }
__device__ __forceinline__ float2 csub(float2 a, float2 b){ return make_float2(a.x-b.x, a.y-b.y); }
__device__ __forceinline__ float2 cmul(float2 a, float2 b){ return make_float2(a.x*b.x - a.y*b.y, a.x*b.y + a.y*b.x); }
__device__ __forceinline__ float2 cmulc(float2 a, float2 b){ // a * conj(b)
    return make_float2(a.x*b.x + a.y*b.y, a.y*b.x - a.x*b.y); }
__device__ __forceinline__ int pp(int i){ return i + (i >> 5); }

// ---- K0: twiddles + zero flags ----
__global__ void init_kernel(){
    int i = blockIdx.x * blockDim.x + threadIdx.x;
    if (i < 4096){
        float s, c;
        sincospif((float)i / 4096.0f, &s, &c);
        d_W[i] = make_float2(c, -s);               // W^k = e^{-2pi i k/8192}
    }
    if (i < 64) d_flags[i] = 0;
}

// ---- K1: A = [Re(C'), -Im(C')] where C' = C*(e^lam-1)/lam ----
__global__ void ct_kernel(const float* __restrict__ Lr, const float* __restrict__ Li,
                          const float* __restrict__ Cr, const float* __restrict__ Ci){
    int idx = blockIdx.x * blockDim.x + threadIdx.x;
    if (idx >= Hn * Nn) return;
    int h = idx >> 9, n = idx & 511;
    float re = -expf(Lr[n]);
    float im =  expf(Li[n]);
    float er = expf(re);
    float s, c; sincosf(im, &s, &c);
    float numx = er * c - 1.0f, numy = er * s;
    float d2 = re * re + im * im;
    float gx = (numx * re + numy * im) / d2;
    float gy = (numy * re - numx * im) / d2;
    float cr = Cr[idx], ci = Ci[idx];
    d_A[h * KDIM + n]       = cr * gx - ci * gy;
    d_A[h * KDIM + 512 + n] = -(cr * gy + ci * gx);
}

// ---- K2: S rows (stacked re/im) + liveness flags ----
__global__ void smat_kernel(const float* __restrict__ Lr, const float* __restrict__ Li){
    int n = blockIdx.y;
    int l = blockIdx.x * 256 + threadIdx.x;
    float re = -expf(Lr[n]);
    float im =  expf(Li[n]);
    float fl = (float)l;
    float decay = expf(re * fl);
    float s, c; sincosf(im * fl, &s, &c);
    d_Bm[n * Ln + l]         = decay * c;
    d_Bm[(512 + n) * Ln + l] = decay * s;
    if (decay >= 1e-20f) d_flags[l >> 6] = 1;
}

// ---- K3: K = A @ S (64x64 tiles, 128 thr, dead-tile skip) ----
__global__ void gemm_kernel(){
    int l0 = blockIdx.x * 64, h0 = blockIdx.y * 64;
    int tid = threadIdx.x;
    int tx = tid & 7, ty = tid >> 3;
    if (d_flags[blockIdx.x] == 0){
        #pragma unroll
        for (int i = 0; i < 4; ++i)
            #pragma unroll
            for (int j = 0; j < 8; ++j)
                d_Kt[(size_t)(h0 + ty*4 + i) * Ln + l0 + tx*8 + j] = 0.0f;
        return;
    }
    __shared__ float As[64][17];
    __shared__ float Bs[16][64];
    float acc[4][8];
    #pragma unroll
    for (int i = 0; i < 4; ++i)
        #pragma unroll
        for (int j = 0; j < 8; ++j) acc[i][j] = 0.0f;
    for (int k0 = 0; k0 < KDIM; k0 += 16){
        #pragma unroll
        for (int q = 0; q < 8; ++q){
            int idx = tid + q * 128;
            As[idx >> 4][idx & 15] = d_A[(h0 + (idx >> 4)) * KDIM + k0 + (idx & 15)];
        }
        #pragma unroll
        for (int q = 0; q < 8; ++q){
            int idx = tid + q * 128;
            Bs[idx >> 6][idx & 63] = d_Bm[(size_t)(k0 + (idx >> 6)) * Ln + l0 + (idx & 63)];
        }
        __syncthreads();
        #pragma unroll
        for (int kk = 0; kk < 16; ++kk){
            float a0 = As[ty*4+0][kk], a1 = As[ty*4+1][kk];
            float a2 = As[ty*4+2][kk], a3 = As[ty*4+3][kk];
            #pragma unroll
            for (int j = 0; j < 8; ++j){
                float bb = Bs[kk][tx*8 + j];
                acc[0][j] += a0 * bb; acc[1][j] += a1 * bb;
                acc[2][j] += a2 * bb; acc[3][j] += a3 * bb;
            }
        }
        __syncthreads();
    }
    #pragma unroll
    for (int i = 0; i < 4; ++i)
        #pragma unroll
        for (int j = 0; j < 8; ++j)
            d_Kt[(size_t)(h0 + ty*4 + i) * Ln + l0 + tx*8 + j] = acc[i][j];
}

// ---- forward DIF: strides 4096..2 as 4 radix-8 passes ----
__device__ void fft8_fwd(float2* X, const float2* W, int tid){
    #pragma unroll
    for (int pi = 0; pi < 4; ++pi){
        const int s = 4096 >> (3 * pi);
        const int quart = s >> 2;
        const int f1 = 4096 / s;
        #pragma unroll
        for (int it = 0; it < 4; ++it){
            int g = tid + (it << 8);
            int j = g & (quart - 1);
            int Bb = g >> (10 - 3 * pi);
            int base = Bb * (s << 1) + j;
            float2 r[8];
            #pragma unroll
            for (int m = 0; m < 8; ++m) r[m] = X[pp(base + m * quart)];
            #pragma unroll
            for (int m = 0; m < 4; ++m){                     // stride s
                float2 a = r[m], b = r[m+4];
                r[m] = cadd(a, b);
                r[m+4] = cmul(csub(a, b), W[(j + m * quart) * f1]);
            }
            {                                                 // stride s/2
                float2 w0 = W[j * (f1 << 1)];
                float2 w1 = W[(j + quart) * (f1 << 1)];
                #pragma unroll
                for (int hh = 0; hh < 2; ++hh){
                    int mb = hh * 4;
                    float2 a = r[mb],   b = r[mb+2];
                    r[mb]   = cadd(a, b); r[mb+2] = cmul(csub(a, b), w0);
                    a = r[mb+1]; b = r[mb+3];
                    r[mb+1] = cadd(a, b); r[mb+3] = cmul(csub(a, b), w1);
                }
            }
            {                                                 // stride s/4
                float2 w3 = W[j * (f1 << 2)];
                #pragma unroll
                for (int m = 0; m < 8; m += 2){
                    float2 a = r[m], b = r[m+1];
                    r[m] = cadd(a, b); r[m+1] = cmul(csub(a, b), w3);
                }
            }
            #pragma unroll
            for (int m = 0; m < 8; ++m) X[pp(base + m * quart)] = r[m];
        }
        __syncthreads();
    }
}

// ---- inverse conjugate DIT: strides 2..4096 as 4 radix-8 passes ----
__device__ void fft8_inv(float2* X, const float2* W, int tid){
    #pragma unroll
    for (int pi = 0; pi < 4; ++pi){
        const int s = 8 << (3 * pi);
        const int quart = s >> 2;
        const int f1 = 4096 / s;
        #pragma unroll
        for (int it = 0; it < 4; ++it){
            int g = tid + (it << 8);
            int j = g & (quart - 1);
            int Bb = g >> (1 + 3 * pi);
            int base = Bb * (s << 1) + j;
            float2 r[8];
            #pragma unroll
            for (int m = 0; m < 8; ++m) r[m] = X[pp(base + m * quart)];
            {                                                 // stride s/4
                float2 w3 = W[j * (f1 << 2)];
                #pragma unroll
                for (int m = 0; m < 8; m += 2){
                    float2 a = r[m], bq = cmulc(r[m+1], w3);
                    r[m] = cadd(a, bq); r[m+1] = csub(a, bq);
                }
            }
            {                                                 // stride s/2
                float2 w0 = W[j * (f1 << 1)];
                float2 w1 = W[(j + quart) * (f1 << 1)];
                #pragma unroll
                for (int hh = 0; hh < 2; ++hh){
                    int mb = hh * 4;
                    float2 a = r[mb],  bq = cmulc(r[mb+2], w0);
                    r[mb] = cadd(a, bq); r[mb+2] = csub(a, bq);
                    a = r[mb+1]; bq = cmulc(r[mb+3], w1);
                    r[mb+1] = cadd(a, bq); r[mb+3] = csub(a, bq);
                }
            }
            #pragma unroll
            for (int m = 0; m < 4; ++m){                     // stride s
                float2 a = r[m], bq = cmulc(r[m+4], W[(j + m * quart) * f1]);
                r[m] = cadd(a, bq); r[m+4] = csub(a, bq);
            }
            #pragma unroll
            for (int m = 0; m < 8; ++m) X[pp(base + m * quart)] = r[m];
        }
        __syncthreads();
    }
}

// ---- K4: scrambled spectrum of K rows ----
__global__ void __launch_bounds__(256) fftK_kernel(){
    extern __shared__ float2 sm[];
    float2* X = sm;
    float2* Wsh = sm + XPAD;
    int h = blockIdx.x, tid = threadIdx.x;
    for (int i = tid; i < 4096; i += 256) Wsh[i] = d_W[i];
    const float* Krow = d_Kt + (size_t)h * Ln;
    for (int i = tid; i < Mn; i += 256){
        float v = (i < Ln) ? Krow[i] : 0.0f;
        X[pp(i)] = make_float2(v, 0.0f);
    }
    __syncthreads();
    fft8_fwd(X, Wsh, tid);
    #pragma unroll
    for (int it = 0; it < 16; ++it){                          // final s=1 stage
        int g = tid + (it << 8);
        int i0 = pp(2*g), i1 = pp(2*g+1);
        float2 a = X[i0], b = X[i1];
        X[i0] = cadd(a, b); X[i1] = csub(a, b);
    }
    __syncthreads();
    float2* Kf = d_Kf + (size_t)h * Mn;
    for (int i = tid; i < Mn; i += 256) Kf[i] = X[pp(i)];
}

// ---- K5: LayerNorm over H (one pass) ----
__global__ void __launch_bounds__(512) ln_kernel(const float* __restrict__ x,
                                                 const float* __restrict__ w,
                                                 const float* __restrict__ b){
    int row = blockIdx.x, tid = threadIdx.x;
    float v = x[(size_t)row * Hn + tid];
    __shared__ float rs[16], rq[16];
    __shared__ float s_mean, s_var;
    float s = v, q = v * v;
    #pragma unroll
    for (int o = 16; o > 0; o >>= 1){
        s += __shfl_xor_sync(0xffffffff, s, o);
        q += __shfl_xor_sync(0xffffffff, q, o);
    }
    if ((tid & 31) == 0){ rs[tid >> 5] = s; rq[tid >> 5] = q; }
    __syncthreads();
    if (tid < 32){
        float ts = (tid < 16) ? rs[tid] : 0.0f;
        float tq = (tid < 16) ? rq[tid] : 0.0f;
        #pragma unroll
        for (int o = 8; o > 0; o >>= 1){
            ts += __shfl_xor_sync(0xffffffff, ts, o);
            tq += __shfl_xor_sync(0xffffffff, tq, o);
        }
        if (tid == 0){
            float mean = ts * (1.0f / Hn);
            s_mean = mean;
            s_var = tq * (1.0f / Hn) - mean * mean;
        }
    }
    __syncthreads();
    float inv = rsqrtf(s_var + 1e-5f);
    d_u[(size_t)row * Hn + tid] = (v - s_mean) * inv * w[tid] + b[tid];
}

// ---- K6: transpose u [B,L,H] -> ut [B,H,L] ----
__global__ void tr_fwd_kernel(){
    __shared__ float tile[32][33];
    int l0 = blockIdx.x * 32, h0 = blockIdx.y * 32, bb = blockIdx.z;
    int tx = threadIdx.x, ty = threadIdx.y;
    #pragma unroll
    for (int r = 0; r < 4; ++r){
        int ly = ty + r * 8;
        tile[ly][tx] = d_u[((size_t)(bb * Ln + l0 + ly)) * Hn + h0 + tx];
    }
    __syncthreads();
    #pragma unroll
    for (int r = 0; r < 4; ++r){
        int hy = ty + r * 8;
        d_ut[((size_t)(bb * Hn + h0 + hy)) * Ln + l0 + tx] = tile[tx][hy];
    }
}

// ---- K7: per-(b,h) scramble-domain FFT convolution ----
__global__ void __launch_bounds__(256) conv_kernel(){
    extern __shared__ float2 sm[];
    float2* X = sm;
    float2* Wsh = sm + XPAD;
    int row = blockIdx.x;
    int h = row & 511;
    int tid = threadIdx.x;
    for (int i = tid; i < 4096; i += 256) Wsh[i] = d_W[i];
    const float* ur = d_ut + (size_t)row * Ln;
    for (int i = tid; i < Mn; i += 256){
        float v = (i < Ln) ? ur[i] : 0.0f;
        X[pp(i)] = make_float2(v, 0.0f);
    }
    __syncthreads();
    fft8_fwd(X, Wsh, tid);
    // fused: final fwd s=1 stage + pointwise multiply + first inverse s=1 stage
    const float2* Kf = d_Kf + (size_t)h * Mn;
    #pragma unroll
    for (int it = 0; it < 16; ++it){
        int g = tid + (it << 8);
        int i0 = pp(2*g), i1 = pp(2*g+1);
        float2 a = X[i0], b = X[i1];
        float2 P = cmul(cadd(a, b), Kf[2*g]);
        float2 Q = cmul(csub(a, b), Kf[2*g+1]);
        X[i0] = cadd(P, Q); X[i1] = csub(P, Q);
    }
    __syncthreads();
    fft8_inv(X, Wsh, tid);
    float* yr = d_yt + (size_t)row * Ln;
    const float inv = 1.0f / 8192.0f;
    for (int i = tid; i < Ln; i += 256) yr[i] = X[pp(i)].x * inv;
}

// ---- K8: transpose back + residual ----
__global__ void final_kernel(const float* __restrict__ D, float* __restrict__ out){
    __shared__ float tile[32][33];
    int l0 = blockIdx.x * 32, h0 = blockIdx.y * 32, bb = blockIdx.z;
    int tx = threadIdx.x, ty = threadIdx.y;
    #pragma unroll
    for (int r = 0; r < 4; ++r){
        int hy = ty + r * 8;
        tile[tx][hy] = d_yt[((size_t)(bb * Hn + h0 + hy)) * Ln + l0 + tx];
    }
    __syncthreads();
    float dh = D[h0 + tx];
    #pragma unroll
    for (int r = 0; r < 4; ++r){
        int ly = ty + r * 8;
        size_t idx = ((size_t)(bb * Ln + l0 + ly)) * Hn + h0 + tx;
        out[idx] = tile[ly][tx] + dh * d_u[idx];
    }
}

extern "C" void kernel_launch(void* const* d_in, const int* in_sizes, int n_in,
                              void* d_out, int out_size) {
    const float* x  = (const float*)d_in[0];
    const float* lw = (const float*)d_in[1];
    const float* lb = (const float*)d_in[2];
    const float* Lr = (const float*)d_in[3];
    const float* Li = (const float*)d_in[4];
    const float* Cr = (const float*)d_in[5];
    const float* Ci = (const float*)d_in[6];
    const float* D  = (const float*)d_in[7];
    float* out = (float*)d_out;

    static bool attr_done = false;
    if (!attr_done){
        cudaFuncSetAttribute(fftK_kernel, cudaFuncAttributeMaxDynamicSharedMemorySize, SMEM_FFT);
        cudaFuncSetAttribute(conv_kernel, cudaFuncAttributeMaxDynamicSharedMemorySize, SMEM_FFT);
        attr_done = true;
    }

    init_kernel<<<16, 256>>>();
    ct_kernel<<<(Hn * Nn + 255) / 256, 256>>>(Lr, Li, Cr, Ci);
    smat_kernel<<<dim3(16, Nn), 256>>>(Lr, Li);
    gemm_kernel<<<dim3(Ln / 64, Hn / 64), 128>>>();
    fftK_kernel<<<Hn, 256, SMEM_FFT>>>();
    ln_kernel<<<Bn * Ln, 512>>>(x, lw, lb);
    tr_fwd_kernel<<<dim3(Ln / 32, Hn / 32, Bn), dim3(32, 8)>>>();
    conv_kernel<<<Bn * Hn, 256, SMEM_FFT>>>();
    final_kernel<<<dim3(Ln / 32, Hn / 32, Bn), dim3(32, 8)>>>(D, out);
}

// round 5
// speedup vs baseline: 1.6652x; 1.6652x over previous
#include <cuda_runtime.h>
#include <cuda_bf16.h>
#include <math.h>

#define Bn 8
#define Ln 4096
#define Hn 512
#define Nn 512
#define Mn 8192
#define KDIM 1024

#define XPAD 8448                                  // 8192 + 8192/32
#define SMEM_FFT ((XPAD + 4096) * (int)sizeof(float2))
#define LNSH 513
#define SMEM_LNT ((32 * LNSH + 1024) * (int)sizeof(float))

// ---- device scratch (no allocations allowed) ----
__device__ float2 d_W[4096];
__device__ int    d_rank[Nn];
__device__ int    d_kcnt[64];
__device__ float  d_A[Hn * KDIM];
__device__ float  d_Bm[(size_t)KDIM * Ln];
__device__ float  d_Kt[(size_t)Hn * Ln];
__device__ float2 d_Kf[(size_t)Hn * Mn];
__device__ float  d_ut[(size_t)Bn * Hn * Ln];
__device__ float  d_yt[(size_t)Bn * Hn * Ln];

__device__ __forceinline__ float2 cadd(float2 a, float2 b){ return make_float2(a.x+b.x, a.y+b.y); }
__device__ __forceinline__ float2 csub(float2 a, float2 b){ return make_float2(a.x-b.x, a.y-b.y); }
__device__ __forceinline__ float2 cmul(float2 a, float2 b){ return make_float2(a.x*b.x - a.y*b.y, a.x*b.y + a.y*b.x); }
__device__ __forceinline__ float2 cmulc(float2 a, float2 b){ // a * conj(b)
    return make_float2(a.x*b.x + a.y*b.y, a.y*b.x - a.x*b.y); }
__device__ __forceinline__ int pp(int i){ return i + (i >> 5); }

// ---- K0: twiddles ----
__global__ void init_kernel(){
    int i = blockIdx.x * blockDim.x + threadIdx.x;
    if (i < 4096){
        float s, c;
        sincospif((float)i / 4096.0f, &s, &c);
        d_W[i] = make_float2(c, -s);               // W^k = e^{-2pi i k/8192}
    }
}

// ---- K0b: rank modes by Lr ascending (|lam_re| ascending = slowest decay first) ----
__global__ void rank_kernel(const float* __restrict__ Lr){
    __shared__ float key[Nn];
    int n = threadIdx.x;
    key[n] = Lr[n];
    __syncthreads();
    float kn = key[n];
    int r = 0;
    #pragma unroll 8
    for (int m = 0; m < Nn; ++m){
        float km = key[m];
        r += (km < kn) || (km == kn && m < n);
    }
    d_rank[n] = r;
}

// ---- K0c: per-l-tile live column counts (prefix in sorted order) ----
__global__ void kcnt_kernel(const float* __restrict__ Lr){
    __shared__ int hist[64];
    int tid = threadIdx.x;     // 512
    if (tid < 64) hist[tid] = 0;
    __syncthreads();
    float a = expf(Lr[tid]);   // |lam_re|
    // mode live in tile t iff a * (64 t) < 60   (ln 1e-26 safety margin)
    int tmax = (int)(60.0f / (64.0f * a));
    if (tmax > 63) tmax = 63;
    if (tmax < 0)  tmax = 0;
    atomicAdd(&hist[tmax], 1);
    __syncthreads();
    if (tid == 0){
        int c = 0;
        for (int t = 63; t >= 0; --t){
            c += hist[t];                 // #modes with tmax >= t
            int cols = 2 * c;
            cols = (cols + 15) & ~15;     // round to k-step
            if (cols > KDIM) cols = KDIM;
            d_kcnt[t] = cols;
        }
    }
}

// ---- K1: A columns (sorted, interleaved re/im): C' = C*(e^lam-1)/lam ----
__global__ void ct_kernel(const float* __restrict__ Lr, const float* __restrict__ Li,
                          const float* __restrict__ Cr, const float* __restrict__ Ci){
    int idx = blockIdx.x * blockDim.x + threadIdx.x;
    if (idx >= Hn * Nn) return;
    int h = idx >> 9, n = idx & 511;
    float re = -expf(Lr[n]);
    float im =  expf(Li[n]);
    float er = expf(re);
    float s, c; sincosf(im, &s, &c);
    float numx = er * c - 1.0f, numy = er * s;
    float d2 = re * re + im * im;
    float gx = (numx * re + numy * im) / d2;
    float gy = (numy * re - numx * im) / d2;
    float cr = Cr[idx], ci = Ci[idx];
    int r2 = 2 * d_rank[n];
    d_A[h * KDIM + r2]     = cr * gx - ci * gy;       // Re(C')
    d_A[h * KDIM + r2 + 1] = -(cr * gy + ci * gx);    // -Im(C')
}

// ---- K2: S rows (sorted, interleaved re/im) ----
__global__ void smat_kernel(const float* __restrict__ Lr, const float* __restrict__ Li){
    int n = blockIdx.y;
    int l = blockIdx.x * 256 + threadIdx.x;
    float re = -expf(Lr[n]);
    float im =  expf(Li[n]);
    float fl = (float)l;
    float decay = expf(re * fl);
    float s, c; sincosf(im * fl, &s, &c);
    int r2 = 2 * d_rank[n];
    d_Bm[(size_t)r2 * Ln + l]       = decay * c;
    d_Bm[(size_t)(r2 + 1) * Ln + l] = decay * s;
}

// ---- K3: K = A @ S, per-tile prefix K-loop ----
__global__ void gemm_kernel(){
    int l0 = blockIdx.x * 64, h0 = blockIdx.y * 64;
    int tid = threadIdx.x;
    int tx = tid & 7, ty = tid >> 3;
    int Klive = d_kcnt[blockIdx.x];
    if (Klive == 0){
        #pragma unroll
        for (int i = 0; i < 4; ++i)
            #pragma unroll
            for (int j = 0; j < 8; ++j)
                d_Kt[(size_t)(h0 + ty*4 + i) * Ln + l0 + tx*8 + j] = 0.0f;
        return;
    }
    __shared__ float As[64][17];
    __shared__ float Bs[16][64];
    float acc[4][8];
    #pragma unroll
    for (int i = 0; i < 4; ++i)
        #pragma unroll
        for (int j = 0; j < 8; ++j) acc[i][j] = 0.0f;
    for (int k0 = 0; k0 < Klive; k0 += 16){
        #pragma unroll
        for (int q = 0; q < 8; ++q){
            int idx = tid + q * 128;
            As[idx >> 4][idx & 15] = d_A[(h0 + (idx >> 4)) * KDIM + k0 + (idx & 15)];
        }
        #pragma unroll
        for (int q = 0; q < 8; ++q){
            int idx = tid + q * 128;
            Bs[idx >> 6][idx & 63] = d_Bm[(size_t)(k0 + (idx >> 6)) * Ln + l0 + (idx & 63)];
        }
        __syncthreads();
        #pragma unroll
        for (int kk = 0; kk < 16; ++kk){
            float a0 = As[ty*4+0][kk], a1 = As[ty*4+1][kk];
            float a2 = As[ty*4+2][kk], a3 = As[ty*4+3][kk];
            #pragma unroll
            for (int j = 0; j < 8; ++j){
                float bb = Bs[kk][tx*8 + j];
                acc[0][j] += a0 * bb; acc[1][j] += a1 * bb;
                acc[2][j] += a2 * bb; acc[3][j] += a3 * bb;
            }
        }
        __syncthreads();
    }
    #pragma unroll
    for (int i = 0; i < 4; ++i)
        #pragma unroll
        for (int j = 0; j < 8; ++j)
            d_Kt[(size_t)(h0 + ty*4 + i) * Ln + l0 + tx*8 + j] = acc[i][j];
}

// ---- forward DIF: strides 4096..2 as 4 radix-8 passes ----
__device__ void fft8_fwd(float2* X, const float2* W, int tid){
    #pragma unroll
    for (int pi = 0; pi < 4; ++pi){
        const int s = 4096 >> (3 * pi);
        const int quart = s >> 2;
        const int f1 = 4096 / s;
        #pragma unroll
        for (int it = 0; it < 4; ++it){
            int g = tid + (it << 8);
            int j = g & (quart - 1);
            int Bb = g >> (10 - 3 * pi);
            int base = Bb * (s << 1) + j;
            float2 r[8];
            #pragma unroll
            for (int m = 0; m < 8; ++m) r[m] = X[pp(base + m * quart)];
            #pragma unroll
            for (int m = 0; m < 4; ++m){                     // stride s
                float2 a = r[m], b = r[m+4];
                r[m] = cadd(a, b);
                r[m+4] = cmul(csub(a, b), W[(j + m * quart) * f1]);
            }
            {                                                 // stride s/2
                float2 w0 = W[j * (f1 << 1)];
                float2 w1 = W[(j + quart) * (f1 << 1)];
                #pragma unroll
                for (int hh = 0; hh < 2; ++hh){
                    int mb = hh * 4;
                    float2 a = r[mb],   b = r[mb+2];
                    r[mb]   = cadd(a, b); r[mb+2] = cmul(csub(a, b), w0);
                    a = r[mb+1]; b = r[mb+3];
                    r[mb+1] = cadd(a, b); r[mb+3] = cmul(csub(a, b), w1);
                }
            }
            {                                                 // stride s/4
                float2 w3 = W[j * (f1 << 2)];
                #pragma unroll
                for (int m = 0; m < 8; m += 2){
                    float2 a = r[m], b = r[m+1];
                    r[m] = cadd(a, b); r[m+1] = cmul(csub(a, b), w3);
                }
            }
            #pragma unroll
            for (int m = 0; m < 8; ++m) X[pp(base + m * quart)] = r[m];
        }
        __syncthreads();
    }
}

// ---- inverse conjugate DIT: strides 2..4096 as 4 radix-8 passes ----
__device__ void fft8_inv(float2* X, const float2* W, int tid){
    #pragma unroll
    for (int pi = 0; pi < 4; ++pi){
        const int s = 8 << (3 * pi);
        const int quart = s >> 2;
        const int f1 = 4096 / s;
        #pragma unroll
        for (int it = 0; it < 4; ++it){
            int g = tid + (it << 8);
            int j = g & (quart - 1);
            int Bb = g >> (1 + 3 * pi);
            int base = Bb * (s << 1) + j;
            float2 r[8];
            #pragma unroll
            for (int m = 0; m < 8; ++m) r[m] = X[pp(base + m * quart)];
            {                                                 // stride s/4
                float2 w3 = W[j * (f1 << 2)];
                #pragma unroll
                for (int m = 0; m < 8; m += 2){
                    float2 a = r[m], bq = cmulc(r[m+1], w3);
                    r[m] = cadd(a, bq); r[m+1] = csub(a, bq);
                }
            }
            {                                                 // stride s/2
                float2 w0 = W[j * (f1 << 1)];
                float2 w1 = W[(j + quart) * (f1 << 1)];
                #pragma unroll
                for (int hh = 0; hh < 2; ++hh){
                    int mb = hh * 4;
                    float2 a = r[mb],  bq = cmulc(r[mb+2], w0);
                    r[mb] = cadd(a, bq); r[mb+2] = csub(a, bq);
                    a = r[mb+1]; bq = cmulc(r[mb+3], w1);
                    r[mb+1] = cadd(a, bq); r[mb+3] = csub(a, bq);
                }
            }
            #pragma unroll
            for (int m = 0; m < 4; ++m){                     // stride s
                float2 a = r[m], bq = cmulc(r[m+4], W[(j + m * quart) * f1]);
                r[m] = cadd(a, bq); r[m+4] = csub(a, bq);
            }
            #pragma unroll
            for (int m = 0; m < 8; ++m) X[pp(base + m * quart)] = r[m];
        }
        __syncthreads();
    }
}

// ---- K4: scrambled spectrum of K rows ----
__global__ void __launch_bounds__(256) fftK_kernel(){
    extern __shared__ float2 sm[];
    float2* X = sm;
    float2* Wsh = sm + XPAD;
    int h = blockIdx.x, tid = threadIdx.x;
    for (int i = tid; i < 4096; i += 256) Wsh[i] = d_W[i];
    const float* Krow = d_Kt + (size_t)h * Ln;
    for (int i = tid; i < Mn; i += 256){
        float v = (i < Ln) ? Krow[i] : 0.0f;
        X[pp(i)] = make_float2(v, 0.0f);
    }
    __syncthreads();
    fft8_fwd(X, Wsh, tid);
    #pragma unroll
    for (int it = 0; it < 16; ++it){                          // final s=1 stage
        int g = tid + (it << 8);
        int i0 = pp(2*g), i1 = pp(2*g+1);
        float2 a = X[i0], b = X[i1];
        X[i0] = cadd(a, b); X[i1] = csub(a, b);
    }
    __syncthreads();
    float2* Kf = d_Kf + (size_t)h * Mn;
    for (int i = tid; i < Mn; i += 256) Kf[i] = X[pp(i)];
}

// ---- K5: fused LayerNorm + transpose: x [B,L,H] -> u^T [B,H,L] ----
__global__ void __launch_bounds__(256) lnt_kernel(const float* __restrict__ x,
                                                  const float* __restrict__ w,
                                                  const float* __restrict__ b){
    extern __shared__ float sh[];                 // [32*LNSH] tile + w/b copies
    float* sw = sh + 32 * LNSH;
    float* sb = sw + 512;
    __shared__ float s_mean[32], s_inv[32];
    int l0 = blockIdx.x * 32, bb = blockIdx.y;
    int tid = threadIdx.x;
    int warp = tid >> 5, lane = tid & 31;

    const float* xr = x + ((size_t)(bb * Ln + l0)) * Hn;  // 32 contiguous rows
    #pragma unroll
    for (int k = 0; k < 64; ++k){
        int i = tid + k * 256;
        sh[(i >> 9) * LNSH + (i & 511)] = xr[i];
    }
    for (int i = tid; i < 512; i += 256){ sw[i] = w[i]; sb[i] = b[i]; }
    __syncthreads();

    for (int r = warp; r < 32; r += 8){
        float s = 0.0f, q = 0.0f;
        #pragma unroll
        for (int k = 0; k < 16; ++k){
            float v = sh[r * LNSH + lane + k * 32];
            s += v; q += v * v;
        }
        #pragma unroll
        for (int o = 16; o > 0; o >>= 1){
            s += __shfl_xor_sync(0xffffffff, s, o);
            q += __shfl_xor_sync(0xffffffff, q, o);
        }
        if (lane == 0){
            float mean = s * (1.0f / Hn);
            s_mean[r] = mean;
            s_inv[r] = rsqrtf(q * (1.0f / Hn) - mean * mean + 1e-5f);
        }
    }
    __syncthreads();

    float mean = s_mean[lane], inv = s_inv[lane];   // lane = l offset
    for (int h = warp; h < 512; h += 8){
        float val = (sh[lane * LNSH + h] - mean) * inv * sw[h] + sb[h];
        d_ut[((size_t)(bb * Hn + h)) * Ln + l0 + lane] = val;
    }
}

// ---- K6: batch-paired scramble-domain FFT convolution ----
__global__ void __launch_bounds__(256) conv_kernel(){
    extern __shared__ float2 sm[];
    float2* X = sm;
    float2* Wsh = sm + XPAD;
    int bp = blockIdx.x >> 9;         // batch pair 0..3
    int h  = blockIdx.x & 511;
    int tid = threadIdx.x;
    for (int i = tid; i < 4096; i += 256) Wsh[i] = d_W[i];
    const float* u0 = d_ut + ((size_t)(2 * bp) * Hn + h) * Ln;
    const float* u1 = u0 + (size_t)Hn * Ln;
    for (int i = tid; i < Mn; i += 256){
        X[pp(i)] = (i < Ln) ? make_float2(u0[i], u1[i]) : make_float2(0.0f, 0.0f);
    }
    __syncthreads();
    fft8_fwd(X, Wsh, tid);
    // fused: final fwd s=1 stage + pointwise multiply + first inverse s=1 stage
    const float2* Kf = d_Kf + (size_t)h * Mn;
    #pragma unroll
    for (int it = 0; it < 16; ++it){
        int g = tid + (it << 8);
        int i0 = pp(2*g), i1 = pp(2*g+1);
        float2 a = X[i0], b = X[i1];
        float2 P = cmul(cadd(a, b), Kf[2*g]);
        float2 Q = cmul(csub(a, b), Kf[2*g+1]);
        X[i0] = cadd(P, Q); X[i1] = csub(P, Q);
    }
    __syncthreads();
    fft8_inv(X, Wsh, tid);
    float* y0 = d_yt + ((size_t)(2 * bp) * Hn + h) * Ln;
    float* y1 = y0 + (size_t)Hn * Ln;
    const float inv = 1.0f / 8192.0f;
    for (int i = tid; i < Ln; i += 256){
        float2 v = X[pp(i)];
        y0[i] = v.x * inv;
        y1[i] = v.y * inv;
    }
}

// ---- K7: transpose back + residual (u taken from d_ut) ----
__global__ void final_kernel(const float* __restrict__ D, float* __restrict__ out){
    __shared__ float ta[32][33], tb[32][33];
    int l0 = blockIdx.x * 32, h0 = blockIdx.y * 32, bb = blockIdx.z;
    int tx = threadIdx.x, ty = threadIdx.y;
    #pragma unroll
    for (int r = 0; r < 4; ++r){
        int hy = ty + r * 8;
        size_t src = ((size_t)(bb * Hn + h0 + hy)) * Ln + l0 + tx;
        ta[tx][hy] = d_yt[src];
        tb[tx][hy] = d_ut[src];
    }
    __syncthreads();
    float dh = D[h0 + tx];
    #pragma unroll
    for (int r = 0; r < 4; ++r){
        int ly = ty + r * 8;
        out[((size_t)(bb * Ln + l0 + ly)) * Hn + h0 + tx] = ta[ly][tx] + dh * tb[ly][tx];
    }
}

extern "C" void kernel_launch(void* const* d_in, const int* in_sizes, int n_in,
                              void* d_out, int out_size) {
    const float* x  = (const float*)d_in[0];
    const float* lw = (const float*)d_in[1];
    const float* lb = (const float*)d_in[2];
    const float* Lr = (const float*)d_in[3];
    const float* Li = (const float*)d_in[4];
    const float* Cr = (const float*)d_in[5];
    const float* Ci = (const float*)d_in[6];
    const float* D  = (const float*)d_in[7];
    float* out = (float*)d_out;

    static bool attr_done = false;
    if (!attr_done){
        cudaFuncSetAttribute(fftK_kernel, cudaFuncAttributeMaxDynamicSharedMemorySize, SMEM_FFT);
        cudaFuncSetAttribute(conv_kernel, cudaFuncAttributeMaxDynamicSharedMemorySize, SMEM_FFT);
        cudaFuncSetAttribute(lnt_kernel,  cudaFuncAttributeMaxDynamicSharedMemorySize, SMEM_LNT);
        attr_done = true;
    }

    init_kernel<<<16, 256>>>();
    rank_kernel<<<1, 512>>>(Lr);
    kcnt_kernel<<<1, 512>>>(Lr);
    ct_kernel<<<(Hn * Nn + 255) / 256, 256>>>(Lr, Li, Cr, Ci);
    smat_kernel<<<dim3(16, Nn), 256>>>(Lr, Li);
    gemm_kernel<<<dim3(Ln / 64, Hn / 64), 128>>>();
    fftK_kernel<<<Hn, 256, SMEM_FFT>>>();
    lnt_kernel<<<dim3(Ln / 32, Bn), 256, SMEM_LNT>>>(x, lw, lb);
    conv_kernel<<<(Bn / 2) * Hn, 256, SMEM_FFT>>>();
    final_kernel<<<dim3(Ln / 32, Hn / 32, Bn), dim3(32, 8)>>>(D, out);
}